// round 10
// baseline (speedup 1.0000x reference)
#include <cuda_runtime.h>
#include <cuda_bf16.h>

#define BB 256
#define TT 4096
#define II 63
#define HH 50
#define FCC 64
#define OO 2
#define CH 8            // steps per chunk (producer->consumer sync grain)
#define NC (TT / CH)    // 512 chunks

// packed fp32x2 FMA (sm_100+)
__device__ __forceinline__ float2 ffma2(float2 a, float2 b, float2 c) {
    unsigned long long ua, ub, uc, ud;
    ua = *reinterpret_cast<unsigned long long*>(&a);
    ub = *reinterpret_cast<unsigned long long*>(&b);
    uc = *reinterpret_cast<unsigned long long*>(&c);
    asm("fma.rn.f32x2 %0, %1, %2, %3;" : "=l"(ud) : "l"(ua), "l"(ub), "l"(uc));
    return *reinterpret_cast<float2*>(&ud);
}

// 2*log2(e): folded into the weights so tanh needs no input scaling
#define TSCALE 2.885390081777926814f

// tanh(x) with p = 2*log2(e)*x prefolded: tanh = 1 - 2/(1 + 2^p)
__device__ __forceinline__ float tanh_scaled(float p) {
    float e, r;
    asm("ex2.approx.f32 %0, %1;" : "=f"(e) : "f"(p));
    asm("rcp.approx.f32 %0, %1;" : "=f"(r) : "f"(e + 1.0f));
    return fmaf(-2.0f, r, 1.0f);
}

// ---------------------------------------------------------------------------
// Warp-specialized fused kernel. 128 CTAs x 256 threads, CTA owns 2 rows.
//   warps 0,1 : recurrence row 0  (lane owns ONE h_j; j = half*32+lane)
//   warps 2,3 : recurrence row 1
//   warps 4,5 : xz producer row 0 (j 0-31 / 32-49); warp 4 also loads x row 0
//   warps 6,7 : xz producer row 1;                  warp 6 also loads x row 1
// Per-step sync = 64-thread NAMED barrier (per row pair). Full __syncthreads
// once per 8-step chunk. xz staged 1 chunk ahead; x staged 3 chunks ahead.
// MLP head + argmax fused at the tail (single kernel launch total).
// ---------------------------------------------------------------------------
__global__ void __launch_bounds__(256, 1)
fused_scan_kernel(const float* __restrict__ x,
                  const float* __restrict__ W_ih,
                  const float* __restrict__ b_ih,
                  const float* __restrict__ W_hh,
                  const float* __restrict__ b_hh,
                  const float* __restrict__ W1,
                  const float* __restrict__ b1,
                  const float* __restrict__ W2,
                  const float* __restrict__ b2,
                  float* __restrict__ out) {
    __shared__ float xs[4][2][CH * 64];     // x ring: [chunk&3][row][t*64+i], 16KB
    __shared__ float xzs[2][2][CH][64];     // xz ring: [chunk&1][row][s][j], 8KB
    __shared__ float hb[2][2][64];          // h double buffer: [buf][row][j]

    const int tid  = threadIdx.x;
    const int wid  = tid >> 5;
    const int lane = tid & 31;

    // zero h buffers (256 threads, 256 floats)
    ((float*)hb)[tid] = 0.f;

    if (wid < 4) {
        // ======================= CONSUMERS (recurrence) ======================
        const int crow  = wid >> 1;            // 0,0,1,1
        const int half  = wid & 1;
        const int j     = half * 32 + lane;    // 0..63
        const int jc    = (j < HH) ? j : HH - 1;
        const bool jv   = (j < HH);
        const int barid = 1 + crow;            // named barrier per row pair

        float2 w[25];
#pragma unroll
        for (int m = 0; m < 25; m++) {
            w[m].x = TSCALE * __ldg(&W_hh[jc * HH + 2 * m]);
            w[m].y = TSCALE * __ldg(&W_hh[jc * HH + 2 * m + 1]);
        }
        const float bh = TSCALE * __ldg(&b_hh[jc]);

        __syncthreads();   // matches producer barrier #1
        __syncthreads();   // matches producer barrier #2 (xz chunk 0 ready)

        for (int c = 0; c < NC; c++) {
            const float* xzrow = &xzs[c & 1][crow][0][0];
#pragma unroll
            for (int s = 0; s < CH; s++) {
                const float xz = xzrow[s * 64 + jc];
                const float*  hp  = hb[s & 1][crow];
                const float4* hp4 = (const float4*)hp;
                float2 a0 = make_float2(xz + bh, 0.f);
                float2 a1 = make_float2(0.f, 0.f);
#pragma unroll
                for (int m = 0; m < 12; m++) {       // h[0..47]
                    float4 hq = hp4[m];
                    a0 = ffma2(make_float2(hq.x, hq.y), w[2 * m], a0);
                    a1 = ffma2(make_float2(hq.z, hq.w), w[2 * m + 1], a1);
                }
                float2 h24 = ((const float2*)hp)[24];  // h48,h49
                a0 = ffma2(h24, w[24], a0);
                float pre = (a0.x + a0.y) + (a1.x + a1.y);
                float hn  = tanh_scaled(pre);
                if (jv) hb[(s & 1) ^ 1][crow][j] = hn;
                asm volatile("bar.sync %0, %1;" :: "r"(barid), "n"(64) : "memory");
            }
            __syncthreads();   // phase boundary (xz ring flip)
        }

        // ================== FUSED MLP HEAD + ARGMAX (tail) ==================
        // h final lives in hb[0][crow][.]; warp with half==0 computes the head.
        if (half == 0) {
            const float* hp = hb[0][crow];
            const int f0 = lane, f1 = lane + 32;
            float d0 = __ldg(&b1[f0]);
            float d1 = __ldg(&b1[f1]);
#pragma unroll
            for (int k = 0; k < HH; k++) {
                float hv = hp[k];
                d0 = fmaf(hv, __ldg(&W1[f0 * HH + k]), d0);
                d1 = fmaf(hv, __ldg(&W1[f1 * HH + k]), d1);
            }
            d0 = fmaxf(d0, 0.f);
            d1 = fmaxf(d1, 0.f);
            float p0 = d0 * __ldg(&W2[f0]) + d1 * __ldg(&W2[f1]);
            float p1 = d0 * __ldg(&W2[FCC + f0]) + d1 * __ldg(&W2[FCC + f1]);
#pragma unroll
            for (int off = 16; off > 0; off >>= 1) {
                p0 += __shfl_xor_sync(0xFFFFFFFFu, p0, off);
                p1 += __shfl_xor_sync(0xFFFFFFFFu, p1, off);
            }
            if (lane == 0) {
                float l0 = p0 + __ldg(&b2[0]);
                float l1 = p1 + __ldg(&b2[1]);
                // softmax monotone; jnp.argmax takes FIRST max -> strict >
                out[blockIdx.x * 2 + crow] = (l1 > l0) ? 1.0f : 0.0f;
            }
        }
    } else {
        // ==================== PRODUCERS (xz) + LOADERS (x) ===================
        const int prow   = (wid - 4) >> 1;              // 0,0,1,1
        const int pj     = (wid & 1) * 32 + lane;       // produced j
        const int pjc    = (pj < HH) ? pj : HH - 1;
        const bool pjv   = (pj < HH);
        const bool loader = ((wid & 1) == 0);           // warps 4,6

        float2 wip[31];
#pragma unroll
        for (int i = 0; i < 31; i++) {
            wip[i].x = TSCALE * __ldg(&W_ih[pjc * II + 2 * i]);
            wip[i].y = TSCALE * __ldg(&W_ih[pjc * II + 2 * i + 1]);
        }
        const float wi62 = TSCALE * __ldg(&W_ih[pjc * II + 62]);
        const float bi   = TSCALE * __ldg(&b_ih[pjc]);

        const float* xldbase = x + (size_t)(blockIdx.x * 2 + prow) * TT * II;

        // loader lane pattern: f = q*32+lane covers 504 floats per chunk
        int offq[16], fqv[16];
#pragma unroll
        for (int q = 0; q < 16; q++) {
            int f = q * 32 + lane;
            fqv[q] = f;
            int t  = f / 63;
            offq[q] = t * 64 + (f - 63 * t);   // padded [t][i] layout
        }

        auto dotx = [&](const float* xr) -> float {
            const float4* xp4 = (const float4*)xr;
            float2 u0 = make_float2(bi, 0.f);
            float2 u1 = make_float2(0.f, 0.f);
#pragma unroll
            for (int n = 0; n < 15; n++) {
                float4 q = xp4[n];
                u0 = ffma2(make_float2(q.x, q.y), wip[2 * n], u0);
                u1 = ffma2(make_float2(q.z, q.w), wip[2 * n + 1], u1);
            }
            float4 q15 = xp4[15];   // x60,x61,x62,(pad)
            u0 = ffma2(make_float2(q15.x, q15.y), wip[30], u0);
            return (u0.x + u0.y) + (u1.x + u1.y) + q15.z * wi62;
        };

        float rld[16];
        // ---- prologue: chunks 0,1 -> smem; chunk 2 -> regs ----
        if (loader) {
#pragma unroll
            for (int q = 0; q < 16; q++)
                if (fqv[q] < CH * II) rld[q] = __ldg(xldbase + fqv[q]);
#pragma unroll
            for (int q = 0; q < 16; q++)
                if (fqv[q] < CH * II) xs[0][prow][offq[q]] = rld[q];
#pragma unroll
            for (int q = 0; q < 16; q++)
                if (fqv[q] < CH * II) rld[q] = __ldg(xldbase + CH * II + fqv[q]);
#pragma unroll
            for (int q = 0; q < 16; q++)
                if (fqv[q] < CH * II) xs[1][prow][offq[q]] = rld[q];
#pragma unroll
            for (int q = 0; q < 16; q++)
                if (fqv[q] < CH * II) rld[q] = __ldg(xldbase + 2 * CH * II + fqv[q]);
        }
        __syncthreads();   // barrier #1: x chunks 0,1 visible

        // xz chunk 0 (this warp's row + j-half)
        {
            const float* x0 = &xs[0][prow][0];
#pragma unroll 4
            for (int s = 0; s < CH; s++) {
                float v = dotx(x0 + s * 64);
                if (pjv) xzs[0][prow][s][pj] = v;
            }
        }
        __syncthreads();   // barrier #2: xz chunk 0 ready

        for (int c = 0; c < NC; c++) {
            // stage x chunk c+2 (regs loaded one phase ago -> landed)
            if (loader && c + 2 < NC) {
#pragma unroll
                for (int q = 0; q < 16; q++)
                    if (fqv[q] < CH * II) xs[(c + 2) & 3][prow][offq[q]] = rld[q];
            }
            // issue LDG for x chunk c+3
            if (loader && c + 3 < NC) {
#pragma unroll
                for (int q = 0; q < 16; q++)
                    if (fqv[q] < CH * II)
                        rld[q] = __ldg(xldbase + (size_t)(c + 3) * CH * II + fqv[q]);
            }
            // compute xz chunk c+1 while consumers chew chunk c
            if (c + 1 < NC) {
                const float* x0 = &xs[(c + 1) & 3][prow][0];
                float* z = &xzs[(c + 1) & 1][prow][0][0];
#pragma unroll 4
                for (int s = 0; s < CH; s++) {
                    float v = dotx(x0 + s * 64);
                    if (pjv) z[s * 64 + pj] = v;
                }
            }
            __syncthreads();   // phase boundary
        }
    }
}

// ---------------------------------------------------------------------------
extern "C" void kernel_launch(void* const* d_in, const int* in_sizes, int n_in,
                              void* d_out, int out_size) {
    const float* x    = (const float*)d_in[0];
    const float* W_ih = (const float*)d_in[1];
    const float* b_ih = (const float*)d_in[2];
    const float* W_hh = (const float*)d_in[3];
    const float* b_hh = (const float*)d_in[4];
    const float* W1   = (const float*)d_in[5];
    const float* b1   = (const float*)d_in[6];
    const float* W2   = (const float*)d_in[7];
    const float* b2   = (const float*)d_in[8];
    float* out = (float*)d_out;

    // single fused kernel: projection + scan + MLP head + argmax.
    // 128 CTAs x 256 thr (8 warps), 1 CTA/SM; each SMSP hosts exactly
    // 1 consumer warp + 1 producer warp.
    fused_scan_kernel<<<128, 256>>>(x, W_ih, b_ih, W_hh, b_hh,
                                    W1, b1, W2, b2, out);
}

// round 14
// speedup vs baseline: 1.1267x; 1.1267x over previous
#include <cuda_runtime.h>
#include <cuda_bf16.h>

#define BB 256
#define TT 4096
#define II 63
#define HH 50
#define FCC 64
#define OO 2
#define CH 8            // steps per chunk (producer->consumer sync grain)
#define NC (TT / CH)    // 512 chunks

// packed fp32x2 FMA (sm_100+)
__device__ __forceinline__ float2 ffma2(float2 a, float2 b, float2 c) {
    unsigned long long ua, ub, uc, ud;
    ua = *reinterpret_cast<unsigned long long*>(&a);
    ub = *reinterpret_cast<unsigned long long*>(&b);
    uc = *reinterpret_cast<unsigned long long*>(&c);
    asm("fma.rn.f32x2 %0, %1, %2, %3;" : "=l"(ud) : "l"(ua), "l"(ub), "l"(uc));
    return *reinterpret_cast<float2*>(&ud);
}
// packed fp32x2 add
__device__ __forceinline__ float2 add2(float2 a, float2 b) {
    unsigned long long ua, ub, uc;
    ua = *reinterpret_cast<unsigned long long*>(&a);
    ub = *reinterpret_cast<unsigned long long*>(&b);
    asm("add.rn.f32x2 %0, %1, %2;" : "=l"(uc) : "l"(ua), "l"(ub));
    return *reinterpret_cast<float2*>(&uc);
}

// 2*log2(e), prefolded into all weights/biases
#define TSCALE 2.885390081777926814f

// tanh(x) with p = 2*log2(e)*x prefolded: tanh = 1 - 2/(1 + 2^p)
__device__ __forceinline__ float tanh_scaled(float p) {
    float e, r;
    asm("ex2.approx.f32 %0, %1;" : "=f"(e) : "f"(p));
    asm("rcp.approx.f32 %0, %1;" : "=f"(r) : "f"(e + 1.0f));
    return fmaf(-2.0f, r, 1.0f);
}

// compile-time reorder barrier (replaces __syncwarp: warp-private smem,
// convergent branch-free loop body -> HW ordering is already guaranteed)
#define CFENCE() asm volatile("" ::: "memory")

// ---------------------------------------------------------------------------
// Warp-specialized fused kernel. 128 CTAs x 128 threads, CTA owns 2 rows.
//   warp 0: recurrence row 0 (warp-PRIVATE h buffer, lane p owns h[2p],h[2p+1])
//   warp 1: recurrence row 1
//   warp 2: xz producer j 0-31  (both rows) + x loader row 0
//   warp 3: xz producer j 32-49 (both rows) + x loader row 1
// One warp per SMSP; per-step sync inside consumer = compiler fence only.
// Cross-warp sync = __syncthreads once per CH=8 steps.
// MLP head + argmax fused at tail -> single kernel launch.
// ---------------------------------------------------------------------------
__global__ void __launch_bounds__(128, 1)
fused_scan_kernel(const float* __restrict__ x,
                  const float* __restrict__ W_ih,
                  const float* __restrict__ b_ih,
                  const float* __restrict__ W_hh,
                  const float* __restrict__ b_hh,
                  const float* __restrict__ W1,
                  const float* __restrict__ b1,
                  const float* __restrict__ W2,
                  const float* __restrict__ b2,
                  float* __restrict__ out) {
    __shared__ float xs[4][2][CH * 64];     // x ring: [chunk&3][row][t*64+i], 16KB
    __shared__ float xzs[2][2][CH][64];     // xz ring: [chunk&1][row][s][j], 8KB
    __shared__ float hb[2][2][64];          // h dbl buffer: [buf][row][j] (warp-private per row)

    const int tid  = threadIdx.x;
    const int wid  = tid >> 5;
    const int lane = tid & 31;

    // zero h buffers (128 threads x 2)
    ((float*)hb)[tid]       = 0.f;
    ((float*)hb)[tid + 128] = 0.f;

    if (wid < 2) {
        // ======================= CONSUMER (recurrence) =======================
        const int crow = wid;
        const int p    = lane;
        const int j0   = (p < 25) ? 2 * p : 48;   // clamp idle lanes

        float2 w0[25], w1[25];
#pragma unroll
        for (int m = 0; m < 25; m++) {
            w0[m].x = TSCALE * __ldg(&W_hh[j0 * HH + 2 * m]);
            w0[m].y = TSCALE * __ldg(&W_hh[j0 * HH + 2 * m + 1]);
            w1[m].x = TSCALE * __ldg(&W_hh[(j0 + 1) * HH + 2 * m]);
            w1[m].y = TSCALE * __ldg(&W_hh[(j0 + 1) * HH + 2 * m + 1]);
        }
        const float bh0 = TSCALE * __ldg(&b_hh[j0]);
        const float bh1 = TSCALE * __ldg(&b_hh[j0 + 1]);

        __syncthreads();   // matches producer barrier #1
        __syncthreads();   // matches producer barrier #2 (xz chunk 0 ready)

        for (int c = 0; c < NC; c++) {
            const float* xzrow = &xzs[c & 1][crow][0][0];
            // prefetch xz for step 0 of this chunk
            float2 xzc = *(const float2*)(xzrow + 2 * p);
#pragma unroll
            for (int s = 0; s < CH; s++) {
                float2 xzn;
                if (s < CH - 1)
                    xzn = *(const float2*)(xzrow + (s + 1) * 64 + 2 * p);

                const float*  hp  = hb[s & 1][crow];
                const float4* hp4 = (const float4*)hp;
                // 4 accumulator chains per output (depth 7)
                float2 A0 = make_float2(xzc.x + bh0, 0.f);
                float2 A1 = make_float2(0.f, 0.f);
                float2 A2 = make_float2(0.f, 0.f);
                float2 A3 = make_float2(0.f, 0.f);
                float2 C0 = make_float2(xzc.y + bh1, 0.f);
                float2 C1 = make_float2(0.f, 0.f);
                float2 C2 = make_float2(0.f, 0.f);
                float2 C3 = make_float2(0.f, 0.f);
#pragma unroll
                for (int m = 0; m < 12; m++) {         // k-pairs 2m, 2m+1
                    float4 hq = hp4[m];
                    float2 hA = make_float2(hq.x, hq.y);
                    float2 hB = make_float2(hq.z, hq.w);
                    switch (m & 1) {
                    case 0:
                        A0 = ffma2(hA, w0[2 * m], A0);
                        A1 = ffma2(hB, w0[2 * m + 1], A1);
                        C0 = ffma2(hA, w1[2 * m], C0);
                        C1 = ffma2(hB, w1[2 * m + 1], C1);
                        break;
                    default:
                        A2 = ffma2(hA, w0[2 * m], A2);
                        A3 = ffma2(hB, w0[2 * m + 1], A3);
                        C2 = ffma2(hA, w1[2 * m], C2);
                        C3 = ffma2(hB, w1[2 * m + 1], C3);
                        break;
                    }
                }
                float2 h24 = ((const float2*)hp)[24];   // h48,h49
                A2 = ffma2(h24, w0[24], A2);
                C2 = ffma2(h24, w1[24], C2);

                float2 As = add2(add2(A0, A1), add2(A2, A3));
                float2 Cs = add2(add2(C0, C1), add2(C2, C3));
                float hn0 = tanh_scaled(As.x + As.y);
                float hn1 = tanh_scaled(Cs.x + Cs.y);
                if (p < 25)
                    *(float2*)&hb[(s & 1) ^ 1][crow][2 * p] = make_float2(hn0, hn1);
                CFENCE();          // warp-private buffer: compile-order only
                xzc = xzn;
            }
            __syncthreads();       // phase boundary (xz ring flip)
        }

        // ================== FUSED MLP HEAD + ARGMAX (tail) ==================
        // final h lives in hb[0][crow] (last step wrote buf 0)
        {
            const float* hp = hb[0][crow];
            const int f0 = lane, f1 = lane + 32;
            float d0 = __ldg(&b1[f0]);
            float d1 = __ldg(&b1[f1]);
#pragma unroll
            for (int k = 0; k < HH; k++) {
                float hv = hp[k];
                d0 = fmaf(hv, __ldg(&W1[f0 * HH + k]), d0);
                d1 = fmaf(hv, __ldg(&W1[f1 * HH + k]), d1);
            }
            d0 = fmaxf(d0, 0.f);
            d1 = fmaxf(d1, 0.f);
            float p0 = d0 * __ldg(&W2[f0]) + d1 * __ldg(&W2[f1]);
            float p1 = d0 * __ldg(&W2[FCC + f0]) + d1 * __ldg(&W2[FCC + f1]);
#pragma unroll
            for (int off = 16; off > 0; off >>= 1) {
                p0 += __shfl_xor_sync(0xFFFFFFFFu, p0, off);
                p1 += __shfl_xor_sync(0xFFFFFFFFu, p1, off);
            }
            if (lane == 0) {
                float l0 = p0 + __ldg(&b2[0]);
                float l1 = p1 + __ldg(&b2[1]);
                // softmax monotone; jnp.argmax takes FIRST max -> strict >
                out[blockIdx.x * 2 + crow] = (l1 > l0) ? 1.0f : 0.0f;
            }
        }
    } else {
        // ==================== PRODUCER (xz) + LOADER (x) =====================
        const int prow = wid - 2;                       // loader row
        const int pj   = (wid == 2) ? lane : 32 + lane; // produced j
        const int pjc  = (pj < HH) ? pj : HH - 1;
        const bool pjv = (pj < HH);

        float2 wip[31];
#pragma unroll
        for (int i = 0; i < 31; i++) {
            wip[i].x = TSCALE * __ldg(&W_ih[pjc * II + 2 * i]);
            wip[i].y = TSCALE * __ldg(&W_ih[pjc * II + 2 * i + 1]);
        }
        const float wi62 = TSCALE * __ldg(&W_ih[pjc * II + 62]);
        const float bi   = TSCALE * __ldg(&b_ih[pjc]);

        const float* xldbase = x + (size_t)(blockIdx.x * 2 + prow) * TT * II;

        // loader lane pattern: f = q*32+lane covers 504 floats per chunk
        int offq[16], fqv[16];
#pragma unroll
        for (int q = 0; q < 16; q++) {
            int f = q * 32 + lane;
            fqv[q] = f;
            int t  = f / 63;
            offq[q] = t * 64 + (f - 63 * t);   // padded [t][i] layout
        }

        auto dotx = [&](const float* xr) -> float {
            const float4* xp4 = (const float4*)xr;
            float2 u0 = make_float2(bi, 0.f);
            float2 u1 = make_float2(0.f, 0.f);
#pragma unroll
            for (int n = 0; n < 15; n++) {
                float4 q = xp4[n];
                u0 = ffma2(make_float2(q.x, q.y), wip[2 * n], u0);
                u1 = ffma2(make_float2(q.z, q.w), wip[2 * n + 1], u1);
            }
            float4 q15 = xp4[15];   // x60,x61,x62,(pad)
            u0 = ffma2(make_float2(q15.x, q15.y), wip[30], u0);
            return (u0.x + u0.y) + (u1.x + u1.y) + q15.z * wi62;
        };

        float rld[16];
        // ---- prologue: chunks 0,1 -> smem; chunk 2 -> regs ----
#pragma unroll
        for (int q = 0; q < 16; q++)
            if (fqv[q] < CH * II) rld[q] = __ldg(xldbase + fqv[q]);
#pragma unroll
        for (int q = 0; q < 16; q++)
            if (fqv[q] < CH * II) xs[0][prow][offq[q]] = rld[q];
#pragma unroll
        for (int q = 0; q < 16; q++)
            if (fqv[q] < CH * II) rld[q] = __ldg(xldbase + CH * II + fqv[q]);
#pragma unroll
        for (int q = 0; q < 16; q++)
            if (fqv[q] < CH * II) xs[1][prow][offq[q]] = rld[q];
#pragma unroll
        for (int q = 0; q < 16; q++)
            if (fqv[q] < CH * II) rld[q] = __ldg(xldbase + 2 * CH * II + fqv[q]);
        __syncthreads();   // barrier #1: x chunks 0,1 visible

        // xz chunk 0 (both rows, this warp's j-half)
        {
            const float* x0 = &xs[0][0][0];
            const float* x1 = &xs[0][1][0];
#pragma unroll 4
            for (int s = 0; s < CH; s++) {
                float v0 = dotx(x0 + s * 64);
                float v1 = dotx(x1 + s * 64);
                if (pjv) {
                    xzs[0][0][s][pj] = v0;
                    xzs[0][1][s][pj] = v1;
                }
            }
        }
        __syncthreads();   // barrier #2: xz chunk 0 ready

        for (int c = 0; c < NC; c++) {
            // stage x chunk c+2 (regs loaded one phase ago -> landed)
            if (c + 2 < NC) {
#pragma unroll
                for (int q = 0; q < 16; q++)
                    if (fqv[q] < CH * II) xs[(c + 2) & 3][prow][offq[q]] = rld[q];
            }
            // issue LDG for x chunk c+3
            if (c + 3 < NC) {
#pragma unroll
                for (int q = 0; q < 16; q++)
                    if (fqv[q] < CH * II)
                        rld[q] = __ldg(xldbase + (size_t)(c + 3) * CH * II + fqv[q]);
            }
            // compute xz chunk c+1 while consumers chew chunk c
            if (c + 1 < NC) {
                const float* x0 = &xs[(c + 1) & 3][0][0];
                const float* x1 = &xs[(c + 1) & 3][1][0];
                float* z0 = &xzs[(c + 1) & 1][0][0][0];
                float* z1 = &xzs[(c + 1) & 1][1][0][0];
#pragma unroll 4
                for (int s = 0; s < CH; s++) {
                    float v0 = dotx(x0 + s * 64);
                    float v1 = dotx(x1 + s * 64);
                    if (pjv) {
                        z0[s * 64 + pj] = v0;
                        z1[s * 64 + pj] = v1;
                    }
                }
            }
            __syncthreads();   // phase boundary
        }
    }
}

// ---------------------------------------------------------------------------
extern "C" void kernel_launch(void* const* d_in, const int* in_sizes, int n_in,
                              void* d_out, int out_size) {
    const float* x    = (const float*)d_in[0];
    const float* W_ih = (const float*)d_in[1];
    const float* b_ih = (const float*)d_in[2];
    const float* W_hh = (const float*)d_in[3];
    const float* b_hh = (const float*)d_in[4];
    const float* W1   = (const float*)d_in[5];
    const float* b1   = (const float*)d_in[6];
    const float* W2   = (const float*)d_in[7];
    const float* b2   = (const float*)d_in[8];
    float* out = (float*)d_out;

    // single fused kernel: projection + scan + MLP head + argmax.
    // 128 CTAs x 128 thr (4 warps), 1 CTA/SM, exactly 1 warp per SMSP.
    fused_scan_kernel<<<128, 128>>>(x, W_ih, b_ih, W_hh, b_hh,
                                    W1, b1, W2, b2, out);
}

// round 15
// speedup vs baseline: 1.1983x; 1.0635x over previous
#include <cuda_runtime.h>
#include <cuda_bf16.h>

#define BB 256
#define TT 4096
#define II 63
#define HH 50
#define FCC 64
#define OO 2
#define CH 16           // steps per chunk (producer->consumer sync grain)
#define NC (TT / CH)    // 256 chunks
#define SUB 8           // steps per x-staging subchunk (2 subs per chunk)
#define NSUB (TT / SUB) // 512

// packed fp32x2 FMA (sm_100+)
__device__ __forceinline__ float2 ffma2(float2 a, float2 b, float2 c) {
    unsigned long long ua, ub, uc, ud;
    ua = *reinterpret_cast<unsigned long long*>(&a);
    ub = *reinterpret_cast<unsigned long long*>(&b);
    uc = *reinterpret_cast<unsigned long long*>(&c);
    asm("fma.rn.f32x2 %0, %1, %2, %3;" : "=l"(ud) : "l"(ua), "l"(ub), "l"(uc));
    return *reinterpret_cast<float2*>(&ud);
}
// packed fp32x2 add
__device__ __forceinline__ float2 add2(float2 a, float2 b) {
    unsigned long long ua, ub, uc;
    ua = *reinterpret_cast<unsigned long long*>(&a);
    ub = *reinterpret_cast<unsigned long long*>(&b);
    asm("add.rn.f32x2 %0, %1, %2;" : "=l"(uc) : "l"(ua), "l"(ub));
    return *reinterpret_cast<float2*>(&uc);
}

// 2*log2(e), prefolded into all weights/biases
#define TSCALE 2.885390081777926814f

// tanh(x) with p = 2*log2(e)*x prefolded: tanh = 1 - 2/(1 + 2^p)
__device__ __forceinline__ float tanh_scaled(float p) {
    float e, r;
    asm("ex2.approx.f32 %0, %1;" : "=f"(e) : "f"(p));
    asm("rcp.approx.f32 %0, %1;" : "=f"(r) : "f"(e + 1.0f));
    return fmaf(-2.0f, r, 1.0f);
}

// compile-time reorder barrier (warp-private smem, convergent code)
#define CFENCE() asm volatile("" ::: "memory")

// ---------------------------------------------------------------------------
// Warp-specialized fused kernel. 128 CTAs x 128 threads, CTA owns 2 rows.
//   warp 0: recurrence row 0 (warp-private h dbl-buffer, lane p -> h[2p],h[2p+1])
//   warp 1: recurrence row 1
//   warp 2: row 0 producer: x loader + xz for ALL j (jA=lane, jB=32+lane)
//   warp 3: row 1 producer (same, fully self-contained)
// One warp per SMSP. Consumer per-step sync = compiler fence only.
// Cross-warp sync = one __syncthreads per CH=16 steps (xz ring flip).
// b_hh folded into producer bias. MLP head + argmax fused at tail.
// ---------------------------------------------------------------------------
__global__ void __launch_bounds__(128, 1)
fused_scan_kernel(const float* __restrict__ x,
                  const float* __restrict__ W_ih,
                  const float* __restrict__ b_ih,
                  const float* __restrict__ W_hh,
                  const float* __restrict__ b_hh,
                  const float* __restrict__ W1,
                  const float* __restrict__ b1,
                  const float* __restrict__ W2,
                  const float* __restrict__ b2,
                  float* __restrict__ out) {
    __shared__ float xs[2][2][SUB * 64];    // x staging: [row][pingpong][t*64+i], 4KB (warp-private per row)
    __shared__ float xzs[2][2][CH][64];     // xz ring: [chunk&1][row][s][j], 16KB
    __shared__ float hb[2][2][64];          // h dbl buffer: [buf][row][j] (warp-private per row)

    const int tid  = threadIdx.x;
    const int wid  = tid >> 5;
    const int lane = tid & 31;

    // zero h buffers (128 threads x 2)
    ((float*)hb)[tid]       = 0.f;
    ((float*)hb)[tid + 128] = 0.f;

    if (wid < 2) {
        // ======================= CONSUMER (recurrence) =======================
        const int crow = wid;
        const int p    = lane;
        const int j0   = (p < 25) ? 2 * p : 48;   // clamp idle lanes

        float2 w0[25], w1[25];
#pragma unroll
        for (int m = 0; m < 25; m++) {
            w0[m].x = TSCALE * __ldg(&W_hh[j0 * HH + 2 * m]);
            w0[m].y = TSCALE * __ldg(&W_hh[j0 * HH + 2 * m + 1]);
            w1[m].x = TSCALE * __ldg(&W_hh[(j0 + 1) * HH + 2 * m]);
            w1[m].y = TSCALE * __ldg(&W_hh[(j0 + 1) * HH + 2 * m + 1]);
        }

        __syncthreads();   // matches producer prologue barrier (xz chunk 0 ready)

        for (int c = 0; c < NC; c++) {
            const float* xzrow = &xzs[c & 1][crow][0][0];
            // prefetch xz for step 0 of this chunk
            float2 xzc = *(const float2*)(xzrow + 2 * p);
#pragma unroll
            for (int s = 0; s < CH; s++) {
                float2 xzn;
                if (s < CH - 1)
                    xzn = *(const float2*)(xzrow + (s + 1) * 64 + 2 * p);

                const float*  hp  = hb[s & 1][crow];
                const float4* hp4 = (const float4*)hp;
                // 4 accumulator chains per output (b_ih+b_hh prefolded into xz)
                float2 A0 = make_float2(xzc.x, 0.f);
                float2 A1 = make_float2(0.f, 0.f);
                float2 A2 = make_float2(0.f, 0.f);
                float2 A3 = make_float2(0.f, 0.f);
                float2 C0 = make_float2(xzc.y, 0.f);
                float2 C1 = make_float2(0.f, 0.f);
                float2 C2 = make_float2(0.f, 0.f);
                float2 C3 = make_float2(0.f, 0.f);
#pragma unroll
                for (int m = 0; m < 12; m++) {         // k-pairs 2m, 2m+1
                    float4 hq = hp4[m];
                    float2 hA = make_float2(hq.x, hq.y);
                    float2 hB = make_float2(hq.z, hq.w);
                    switch (m & 1) {
                    case 0:
                        A0 = ffma2(hA, w0[2 * m], A0);
                        A1 = ffma2(hB, w0[2 * m + 1], A1);
                        C0 = ffma2(hA, w1[2 * m], C0);
                        C1 = ffma2(hB, w1[2 * m + 1], C1);
                        break;
                    default:
                        A2 = ffma2(hA, w0[2 * m], A2);
                        A3 = ffma2(hB, w0[2 * m + 1], A3);
                        C2 = ffma2(hA, w1[2 * m], C2);
                        C3 = ffma2(hB, w1[2 * m + 1], C3);
                        break;
                    }
                }
                float2 h24 = ((const float2*)hp)[24];   // h48,h49
                A2 = ffma2(h24, w0[24], A2);
                C2 = ffma2(h24, w1[24], C2);

                float2 As = add2(add2(A0, A1), add2(A2, A3));
                float2 Cs = add2(add2(C0, C1), add2(C2, C3));
                float hn0 = tanh_scaled(As.x + As.y);
                float hn1 = tanh_scaled(Cs.x + Cs.y);
                if (p < 25)
                    *(float2*)&hb[(s & 1) ^ 1][crow][2 * p] = make_float2(hn0, hn1);
                CFENCE();          // warp-private buffer: compile-order only
                xzc = xzn;
            }
            __syncthreads();       // phase boundary (xz ring flip)
        }

        // ================== FUSED MLP HEAD + ARGMAX (tail) ==================
        // final h lives in hb[0][crow] (step CH-1 wrote buf 0)
        {
            const float* hp = hb[0][crow];
            const int f0 = lane, f1 = lane + 32;
            float d0 = __ldg(&b1[f0]);
            float d1 = __ldg(&b1[f1]);
#pragma unroll
            for (int k = 0; k < HH; k++) {
                float hv = hp[k];
                d0 = fmaf(hv, __ldg(&W1[f0 * HH + k]), d0);
                d1 = fmaf(hv, __ldg(&W1[f1 * HH + k]), d1);
            }
            d0 = fmaxf(d0, 0.f);
            d1 = fmaxf(d1, 0.f);
            float p0 = d0 * __ldg(&W2[f0]) + d1 * __ldg(&W2[f1]);
            float p1 = d0 * __ldg(&W2[FCC + f0]) + d1 * __ldg(&W2[FCC + f1]);
#pragma unroll
            for (int off = 16; off > 0; off >>= 1) {
                p0 += __shfl_xor_sync(0xFFFFFFFFu, p0, off);
                p1 += __shfl_xor_sync(0xFFFFFFFFu, p1, off);
            }
            if (lane == 0) {
                float l0 = p0 + __ldg(&b2[0]);
                float l1 = p1 + __ldg(&b2[1]);
                // softmax monotone; jnp.argmax takes FIRST max -> strict >
                out[blockIdx.x * 2 + crow] = (l1 > l0) ? 1.0f : 0.0f;
            }
        }
    } else {
        // ============ PRODUCER: one warp fully owns one row ============
        const int prow = wid - 2;
        const int jA   = lane;                 // 0..31, all valid (<50)
        const int jB   = 32 + lane;            // valid lane<18
        const int jBc  = (jB < HH) ? jB : HH - 1;
        const bool jBv = (jB < HH);

        float2 wA[31], wB[31];
#pragma unroll
        for (int i = 0; i < 31; i++) {
            wA[i].x = TSCALE * __ldg(&W_ih[jA * II + 2 * i]);
            wA[i].y = TSCALE * __ldg(&W_ih[jA * II + 2 * i + 1]);
            wB[i].x = TSCALE * __ldg(&W_ih[jBc * II + 2 * i]);
            wB[i].y = TSCALE * __ldg(&W_ih[jBc * II + 2 * i + 1]);
        }
        const float wA62 = TSCALE * __ldg(&W_ih[jA * II + 62]);
        const float wB62 = TSCALE * __ldg(&W_ih[jBc * II + 62]);
        // b_hh folded in here (consumer adds nothing)
        const float bA = TSCALE * (__ldg(&b_ih[jA])  + __ldg(&b_hh[jA]));
        const float bB = TSCALE * (__ldg(&b_ih[jBc]) + __ldg(&b_hh[jBc]));

        const float* xldbase = x + (size_t)(blockIdx.x * 2 + prow) * TT * II;

        float rld[16];
        // load one SUB-step x subchunk into regs (clamped index)
        auto ldg_sub = [&](int sub) {
            if (sub > NSUB - 1) sub = NSUB - 1;
            const float* base = xldbase + (size_t)sub * SUB * II;
#pragma unroll
            for (int q = 0; q < 16; q++) {
                int f = q * 32 + lane;
                if (f < SUB * II) rld[q] = __ldg(base + f);
            }
        };
        // store staged regs into xs[prow][pp] (padded [t][i] layout)
        auto sts_sub = [&](int pp) {
#pragma unroll
            for (int q = 0; q < 16; q++) {
                int f = q * 32 + lane;
                if (f < SUB * II) {
                    int t = f / II;
                    xs[prow][pp][t * 64 + (f - II * t)] = rld[q];
                }
            }
            __syncwarp();   // cross-lane visibility before broadcast reads
        };

        auto dotx = [&](const float* xr, const float2* wip, float w62,
                        float bias) -> float {
            const float4* xp4 = (const float4*)xr;
            float2 u0 = make_float2(bias, 0.f);
            float2 u1 = make_float2(0.f, 0.f);
#pragma unroll
            for (int n = 0; n < 15; n++) {
                float4 q = xp4[n];
                u0 = ffma2(make_float2(q.x, q.y), wip[2 * n], u0);
                u1 = ffma2(make_float2(q.z, q.w), wip[2 * n + 1], u1);
            }
            float4 q15 = xp4[15];   // x60,x61,x62,(pad)
            u0 = ffma2(make_float2(q15.x, q15.y), wip[30], u0);
            return (u0.x + u0.y) + (u1.x + u1.y) + q15.z * w62;
        };

        // compute SUB steps of xz from xs[prow][pp] into zdst[s*64 + j]
        auto compute_half = [&](int pp, float* zdst) {
            const float* xbase = &xs[prow][pp][0];
#pragma unroll 4
            for (int u = 0; u < SUB; u++) {
                const float* xr = xbase + u * 64;
                float vA = dotx(xr, wA, wA62, bA);
                float vB = dotx(xr, wB, wB62, bB);
                zdst[u * 64 + jA] = vA;
                if (jBv) zdst[u * 64 + jB] = vB;
            }
        };

        // ---- prologue: stage subs 0,1; compute chunk 0; stage subs 2,3 ----
        ldg_sub(0); sts_sub(0);
        ldg_sub(1); sts_sub(1);
        compute_half(0, &xzs[0][prow][0][0]);
        compute_half(1, &xzs[0][prow][SUB][0]);
        ldg_sub(2); sts_sub(0);
        ldg_sub(3); sts_sub(1);
        __syncthreads();   // xz chunk 0 ready (consumer prologue barrier)

        // ---- steady state: phase c computes xz chunk c+1 ----
        // invariant at phase start: xs = {sub 2c+2 (ping), sub 2c+3 (pong)}
        for (int c = 0; c < NC; c++) {
            if (c + 1 < NC) {
                ldg_sub(2 * c + 4);                           // in flight over half 1
                compute_half(0, &xzs[(c + 1) & 1][prow][0][0]);
                sts_sub(0);                                   // ping <- sub 2c+4
                ldg_sub(2 * c + 5);                           // in flight over half 2
                compute_half(1, &xzs[(c + 1) & 1][prow][SUB][0]);
                sts_sub(1);                                   // pong <- sub 2c+5
            }
            __syncthreads();   // phase boundary
        }
    }
}

// ---------------------------------------------------------------------------
extern "C" void kernel_launch(void* const* d_in, const int* in_sizes, int n_in,
                              void* d_out, int out_size) {
    const float* x    = (const float*)d_in[0];
    const float* W_ih = (const float*)d_in[1];
    const float* b_ih = (const float*)d_in[2];
    const float* W_hh = (const float*)d_in[3];
    const float* b_hh = (const float*)d_in[4];
    const float* W1   = (const float*)d_in[5];
    const float* b1   = (const float*)d_in[6];
    const float* W2   = (const float*)d_in[7];
    const float* b2   = (const float*)d_in[8];
    float* out = (float*)d_out;

    // single fused kernel: projection + scan + MLP head + argmax.
    // 128 CTAs x 128 thr (4 warps), 1 CTA/SM, exactly 1 warp per SMSP;
    // producers fully own their row (no cross-producer coupling).
    fused_scan_kernel<<<128, 128>>>(x, W_ih, b_ih, W_hh, b_hh,
                                    W1, b1, W2, b2, out);
}

// round 16
// speedup vs baseline: 1.3705x; 1.1437x over previous
#include <cuda_runtime.h>
#include <cuda_bf16.h>

#define BB 256
#define TT 4096
#define II 63
#define HH 50
#define FCC 64
#define OO 2
#define CH 16           // steps per chunk (producer->consumer sync grain)
#define NC (TT / CH)    // 256 chunks
#define EXC 16          // chunks computed with EXACT tanh at the end (256 steps)
#define SUB 8           // steps per x-staging subchunk (2 subs per chunk)
#define NSUB (TT / SUB) // 512

// packed fp32x2 FMA (sm_100+)
__device__ __forceinline__ float2 ffma2(float2 a, float2 b, float2 c) {
    unsigned long long ua, ub, uc, ud;
    ua = *reinterpret_cast<unsigned long long*>(&a);
    ub = *reinterpret_cast<unsigned long long*>(&b);
    uc = *reinterpret_cast<unsigned long long*>(&c);
    asm("fma.rn.f32x2 %0, %1, %2, %3;" : "=l"(ud) : "l"(ua), "l"(ub), "l"(uc));
    return *reinterpret_cast<float2*>(&ud);
}
// packed fp32x2 add
__device__ __forceinline__ float2 add2(float2 a, float2 b) {
    unsigned long long ua, ub, uc;
    ua = *reinterpret_cast<unsigned long long*>(&a);
    ub = *reinterpret_cast<unsigned long long*>(&b);
    asm("add.rn.f32x2 %0, %1, %2;" : "=l"(uc) : "l"(ua), "l"(ub));
    return *reinterpret_cast<float2*>(&uc);
}

#define TSCALE 2.885390081777926814f   // 2*log2(e)

// fast path: single-MUFU hardware tanh (lat 16). err ~5e-4; used for steps
// whose influence on the final state decays through >=256 contraction steps.
__device__ __forceinline__ float tanh_mufu(float v) {
    float r;
    asm("tanh.approx.f32 %0, %1;" : "=f"(r) : "f"(v));
    return r;
}
// exact path (err ~1e-6, proven rel_err 0.0 in r3-r15): 1 - 2/(1+2^(2*log2e*x))
__device__ __forceinline__ float tanh_exact(float v) {
    float e, r;
    float p = v * TSCALE;
    asm("ex2.approx.f32 %0, %1;" : "=f"(e) : "f"(p));
    asm("rcp.approx.f32 %0, %1;" : "=f"(r) : "f"(e + 1.0f));
    return fmaf(-2.0f, r, 1.0f);
}

// compile-time reorder barrier (warp-private smem, convergent code)
#define CFENCE() asm volatile("" ::: "memory")

// one CH-step chunk of the recurrence; TANHFN selects fast/exact tail
#define DO_CHUNK(TANHFN)                                                      \
    {                                                                         \
        const float* xzrow = &xzs[c & 1][crow][0][0];                         \
        float2 xzc = *(const float2*)(xzrow + 2 * p);                         \
        _Pragma("unroll")                                                     \
        for (int s = 0; s < CH; s++) {                                        \
            float2 xzn = *(const float2*)(xzrow +                             \
                             ((s + 1) & (CH - 1)) * 64 + 2 * p);              \
            const float*  hp  = hb[s & 1][crow];                              \
            const float4* hp4 = (const float4*)hp;                            \
            float2 A0 = make_float2(xzc.x, 0.f);                              \
            float2 A1 = make_float2(0.f, 0.f);                                \
            float2 A2 = make_float2(0.f, 0.f);                                \
            float2 A3 = make_float2(0.f, 0.f);                                \
            float2 C0 = make_float2(xzc.y, 0.f);                              \
            float2 C1 = make_float2(0.f, 0.f);                                \
            float2 C2 = make_float2(0.f, 0.f);                                \
            float2 C3 = make_float2(0.f, 0.f);                                \
            _Pragma("unroll")                                                 \
            for (int m = 0; m < 12; m++) {                                    \
                float4 hq = hp4[m];                                           \
                float2 hA = make_float2(hq.x, hq.y);                          \
                float2 hB = make_float2(hq.z, hq.w);                          \
                switch (m & 1) {                                              \
                case 0:                                                       \
                    A0 = ffma2(hA, w0[2 * m], A0);                            \
                    A1 = ffma2(hB, w0[2 * m + 1], A1);                        \
                    C0 = ffma2(hA, w1[2 * m], C0);                            \
                    C1 = ffma2(hB, w1[2 * m + 1], C1);                        \
                    break;                                                    \
                default:                                                      \
                    A2 = ffma2(hA, w0[2 * m], A2);                            \
                    A3 = ffma2(hB, w0[2 * m + 1], A3);                        \
                    C2 = ffma2(hA, w1[2 * m], C2);                            \
                    C3 = ffma2(hB, w1[2 * m + 1], C3);                        \
                    break;                                                    \
                }                                                             \
            }                                                                 \
            float2 h24 = ((const float2*)hp)[24];                             \
            A2 = ffma2(h24, w0[24], A2);                                      \
            C2 = ffma2(h24, w1[24], C2);                                      \
            float2 As = add2(add2(A0, A1), add2(A2, A3));                     \
            float2 Cs = add2(add2(C0, C1), add2(C2, C3));                     \
            float hn0 = TANHFN(As.x + As.y);                                  \
            float hn1 = TANHFN(Cs.x + Cs.y);                                  \
            if (p < 25)                                                       \
                *(float2*)&hb[(s & 1) ^ 1][crow][2 * p] =                     \
                    make_float2(hn0, hn1);                                    \
            CFENCE();                                                         \
            xzc = xzn;                                                        \
        }                                                                     \
    }

// ---------------------------------------------------------------------------
// Warp-specialized fused kernel. 128 CTAs x 128 threads, CTA owns 2 rows.
//   warp 0/1: recurrence row 0/1 (warp-private h dbl-buffer, lane p -> 2 h's)
//   warp 2/3: row 0/1 producer: x loader + xz for ALL j of its row
// One warp per SMSP. Consumer per-step sync = compiler fence only.
// Cross-warp sync = one __syncthreads per CH=16 steps (xz ring flip).
// b_ih+b_hh folded into producer xz. tanh: MUFU fast path + 256-step exact
// tail (contraction absorbs the fast path's 5e-4 error).
// MLP head + argmax fused at tail.
// ---------------------------------------------------------------------------
__global__ void __launch_bounds__(128, 1)
fused_scan_kernel(const float* __restrict__ x,
                  const float* __restrict__ W_ih,
                  const float* __restrict__ b_ih,
                  const float* __restrict__ W_hh,
                  const float* __restrict__ b_hh,
                  const float* __restrict__ W1,
                  const float* __restrict__ b1,
                  const float* __restrict__ W2,
                  const float* __restrict__ b2,
                  float* __restrict__ out) {
    __shared__ float xs[2][2][SUB * 64];    // x staging: [row][pingpong][t*64+i]
    __shared__ float xzs[2][2][CH][64];     // xz ring: [chunk&1][row][s][j], 16KB
    __shared__ float hb[2][2][64];          // h dbl buffer: [buf][row][j]

    const int tid  = threadIdx.x;
    const int wid  = tid >> 5;
    const int lane = tid & 31;

    // zero h buffers (128 threads x 2)
    ((float*)hb)[tid]       = 0.f;
    ((float*)hb)[tid + 128] = 0.f;

    if (wid < 2) {
        // ======================= CONSUMER (recurrence) =======================
        const int crow = wid;
        const int p    = lane;
        const int j0   = (p < 25) ? 2 * p : 48;   // clamp idle lanes

        float2 w0[25], w1[25];
#pragma unroll
        for (int m = 0; m < 25; m++) {
            w0[m].x = __ldg(&W_hh[j0 * HH + 2 * m]);
            w0[m].y = __ldg(&W_hh[j0 * HH + 2 * m + 1]);
            w1[m].x = __ldg(&W_hh[(j0 + 1) * HH + 2 * m]);
            w1[m].y = __ldg(&W_hh[(j0 + 1) * HH + 2 * m + 1]);
        }

        __syncthreads();   // matches producer prologue barrier (xz chunk 0 ready)

        for (int c = 0; c < NC - EXC; c++) {
            DO_CHUNK(tanh_mufu);
            __syncthreads();       // phase boundary (xz ring flip)
        }
        for (int c = NC - EXC; c < NC; c++) {
            DO_CHUNK(tanh_exact);
            __syncthreads();
        }

        // ================== FUSED MLP HEAD + ARGMAX (tail) ==================
        {
            const float* hp = hb[0][crow];
            const int f0 = lane, f1 = lane + 32;
            float d0 = __ldg(&b1[f0]);
            float d1 = __ldg(&b1[f1]);
#pragma unroll
            for (int k = 0; k < HH; k++) {
                float hv = hp[k];
                d0 = fmaf(hv, __ldg(&W1[f0 * HH + k]), d0);
                d1 = fmaf(hv, __ldg(&W1[f1 * HH + k]), d1);
            }
            d0 = fmaxf(d0, 0.f);
            d1 = fmaxf(d1, 0.f);
            float p0 = d0 * __ldg(&W2[f0]) + d1 * __ldg(&W2[f1]);
            float p1 = d0 * __ldg(&W2[FCC + f0]) + d1 * __ldg(&W2[FCC + f1]);
#pragma unroll
            for (int off = 16; off > 0; off >>= 1) {
                p0 += __shfl_xor_sync(0xFFFFFFFFu, p0, off);
                p1 += __shfl_xor_sync(0xFFFFFFFFu, p1, off);
            }
            if (lane == 0) {
                float l0 = p0 + __ldg(&b2[0]);
                float l1 = p1 + __ldg(&b2[1]);
                // softmax monotone; jnp.argmax takes FIRST max -> strict >
                out[blockIdx.x * 2 + crow] = (l1 > l0) ? 1.0f : 0.0f;
            }
        }
    } else {
        // ============ PRODUCER: one warp fully owns one row ============
        const int prow = wid - 2;
        const int jA   = lane;                 // 0..31, all valid (<50)
        const int jB   = 32 + lane;            // valid lane<18
        const int jBc  = (jB < HH) ? jB : HH - 1;
        const bool jBv = (jB < HH);

        float2 wA[31], wB[31];
#pragma unroll
        for (int i = 0; i < 31; i++) {
            wA[i].x = __ldg(&W_ih[jA * II + 2 * i]);
            wA[i].y = __ldg(&W_ih[jA * II + 2 * i + 1]);
            wB[i].x = __ldg(&W_ih[jBc * II + 2 * i]);
            wB[i].y = __ldg(&W_ih[jBc * II + 2 * i + 1]);
        }
        const float wA62 = __ldg(&W_ih[jA * II + 62]);
        const float wB62 = __ldg(&W_ih[jBc * II + 62]);
        // b_hh folded in here (consumer adds nothing)
        const float bA = __ldg(&b_ih[jA])  + __ldg(&b_hh[jA]);
        const float bB = __ldg(&b_ih[jBc]) + __ldg(&b_hh[jBc]);

        const float* xldbase = x + (size_t)(blockIdx.x * 2 + prow) * TT * II;

        float rld[16];
        auto ldg_sub = [&](int sub) {
            if (sub > NSUB - 1) sub = NSUB - 1;
            const float* base = xldbase + (size_t)sub * SUB * II;
#pragma unroll
            for (int q = 0; q < 16; q++) {
                int f = q * 32 + lane;
                if (f < SUB * II) rld[q] = __ldg(base + f);
            }
        };
        auto sts_sub = [&](int pp) {
#pragma unroll
            for (int q = 0; q < 16; q++) {
                int f = q * 32 + lane;
                if (f < SUB * II) {
                    int t = f / II;
                    xs[prow][pp][t * 64 + (f - II * t)] = rld[q];
                }
            }
            __syncwarp();   // cross-lane visibility before broadcast reads
        };

        auto dotx = [&](const float* xr, const float2* wip, float w62,
                        float bias) -> float {
            const float4* xp4 = (const float4*)xr;
            float2 u0 = make_float2(bias, 0.f);
            float2 u1 = make_float2(0.f, 0.f);
#pragma unroll
            for (int n = 0; n < 15; n++) {
                float4 q = xp4[n];
                u0 = ffma2(make_float2(q.x, q.y), wip[2 * n], u0);
                u1 = ffma2(make_float2(q.z, q.w), wip[2 * n + 1], u1);
            }
            float4 q15 = xp4[15];   // x60,x61,x62,(pad)
            u0 = ffma2(make_float2(q15.x, q15.y), wip[30], u0);
            return (u0.x + u0.y) + (u1.x + u1.y) + q15.z * w62;
        };

        auto compute_half = [&](int pp, float* zdst) {
            const float* xbase = &xs[prow][pp][0];
#pragma unroll 4
            for (int u = 0; u < SUB; u++) {
                const float* xr = xbase + u * 64;
                float vA = dotx(xr, wA, wA62, bA);
                float vB = dotx(xr, wB, wB62, bB);
                zdst[u * 64 + jA] = vA;
                if (jBv) zdst[u * 64 + jB] = vB;
            }
        };

        // ---- prologue: stage subs 0,1; compute chunk 0; stage subs 2,3 ----
        ldg_sub(0); sts_sub(0);
        ldg_sub(1); sts_sub(1);
        compute_half(0, &xzs[0][prow][0][0]);
        compute_half(1, &xzs[0][prow][SUB][0]);
        ldg_sub(2); sts_sub(0);
        ldg_sub(3); sts_sub(1);
        __syncthreads();   // xz chunk 0 ready (consumer prologue barrier)

        // ---- steady state: phase c computes xz chunk c+1 ----
        for (int c = 0; c < NC; c++) {
            if (c + 1 < NC) {
                ldg_sub(2 * c + 4);                           // in flight, half 1
                compute_half(0, &xzs[(c + 1) & 1][prow][0][0]);
                sts_sub(0);                                   // ping <- sub 2c+4
                ldg_sub(2 * c + 5);                           // in flight, half 2
                compute_half(1, &xzs[(c + 1) & 1][prow][SUB][0]);
                sts_sub(1);                                   // pong <- sub 2c+5
            }
            __syncthreads();   // phase boundary
        }
    }
}

// ---------------------------------------------------------------------------
extern "C" void kernel_launch(void* const* d_in, const int* in_sizes, int n_in,
                              void* d_out, int out_size) {
    const float* x    = (const float*)d_in[0];
    const float* W_ih = (const float*)d_in[1];
    const float* b_ih = (const float*)d_in[2];
    const float* W_hh = (const float*)d_in[3];
    const float* b_hh = (const float*)d_in[4];
    const float* W1   = (const float*)d_in[5];
    const float* b1   = (const float*)d_in[6];
    const float* W2   = (const float*)d_in[7];
    const float* b2   = (const float*)d_in[8];
    float* out = (float*)d_out;

    // single fused kernel: projection + scan + MLP head + argmax.
    // 128 CTAs x 128 thr (4 warps), 1 CTA/SM, exactly 1 warp per SMSP.
    fused_scan_kernel<<<128, 128>>>(x, W_ih, b_ih, W_hh, b_hh,
                                    W1, b1, W2, b2, out);
}